// round 7
// baseline (speedup 1.0000x reference)
#include <cuda_runtime.h>
#include <math.h>
#include <stdint.h>

#define HIDDEN 4096
#define NEXP   128
#define TOPK   8
#define TM     128
#define TK     8
#define NCHUNK (HIDDEN / TK)          // 512
#define NTHR   512

#define APITCH 1040                   // bytes per k-row of duplicated A (pad 16)
#define WPITCH 528                    // bytes per k-row of B (pad 16)
#define XS_B   (TK * APITCH)          // 8320
#define WS_B   (TK * WPITCH)          // 4224
#define STAGE_B (XS_B + WS_B)         // 12544 (x2 = 25088)
#define LPITCH 132
#define SMEM_BYTES (TM * LPITCH * 4)  // 67584 >= 2*STAGE_B

// packed fp32 FMA: d.lo += a.lo*b.lo ; d.hi += a.hi*b.hi  (IEEE fp32 lanes)
__device__ __forceinline__ void ffma2(unsigned long long& d,
                                      unsigned long long a,
                                      unsigned long long b) {
    asm("fma.rn.f32x2 %0, %1, %2, %0;" : "+l"(d) : "l"(a), "l"(b));
}

// ---------------------------------------------------------------------------
// Fused router: packed-fp32 (f32x2) SGEMM  logits = X @ W^T  -> smem logits
// -> sigmoid -> top-8 (score = sigmoid + bias, lowest-index tie-break)
// -> normalize -> out = [indices_as_float | weights].
// One CTA per 128 tokens, 512 threads (16 warps, 4/SMSP for latency hiding).
// Thread (tx=tid&15, ty=tid>>4) owns 4 tokens x 8 experts (16 packed pairs).
// Numerics bit-identical to scalar fp32 sequential-k accumulation.
// ---------------------------------------------------------------------------
__global__ void __launch_bounds__(NTHR, 1) router_fused(
    const float* __restrict__ X, const float* __restrict__ W,
    const float* __restrict__ bias, float* __restrict__ out, int T)
{
    extern __shared__ char smem[];
    const int tid  = threadIdx.x;
    const int wid  = tid >> 5;
    const int lane = tid & 31;
    const int tx   = tid & 15;         // expert block (8 experts)
    const int ty   = tid >> 4;         // token block (4 tokens), 0..31
    const int m0   = blockIdx.x * TM;

    // producer map: tok/e = tid>>2 (0..127), kp = (tid&3)*2 (k offset 0,2,4,6)
    const int prow = tid >> 2;
    const int kp   = (tid & 3) * 2;

    unsigned long long acc[4][4];
#pragma unroll
    for (int i = 0; i < 4; i++)
#pragma unroll
        for (int j = 0; j < 4; j++) acc[i][j] = 0ull;

    const float* xptr = X + (size_t)(m0 + prow) * HIDDEN + kp;
    const float* wptr = W + (size_t)prow * HIDDEN + kp;

    float2 xa, wa;

    // ---- prologue: chunk 0 -> stage 0 ----
    xa = *(const float2*)(xptr);
    wa = *(const float2*)(wptr);
    {
        char* sp = smem;
        *(float2*)(sp + (kp + 0) * APITCH + prow * 8) = make_float2(xa.x, xa.x);
        *(float2*)(sp + (kp + 1) * APITCH + prow * 8) = make_float2(xa.y, xa.y);
        *(float*)(sp + XS_B + (kp + 0) * WPITCH + prow * 4) = wa.x;
        *(float*)(sp + XS_B + (kp + 1) * WPITCH + prow * 4) = wa.y;
    }

    // ---- main loop ----
    for (int c = 0; c < NCHUNK; c++) {
        __syncthreads();
        const char* sp = smem + (c & 1) * STAGE_B;

        if (c + 1 < NCHUNK) {
            xa = *(const float2*)(xptr + (c + 1) * TK);
            wa = *(const float2*)(wptr + (c + 1) * TK);
        }

#pragma unroll
        for (int kk = 0; kk < TK; kk++) {
            const char* xrow = sp + kk * APITCH + ty * 32;
            const char* wrow = sp + XS_B + kk * WPITCH + tx * 32;

            ulonglong2 a01 = *(const ulonglong2*)(xrow);        // tokens 0,1 (dup)
            ulonglong2 a23 = *(const ulonglong2*)(xrow + 16);   // tokens 2,3 (dup)
            ulonglong2 b01 = *(const ulonglong2*)(wrow);        // expert pairs 0,1
            ulonglong2 b23 = *(const ulonglong2*)(wrow + 16);   // expert pairs 2,3

            unsigned long long ar[4] = {a01.x, a01.y, a23.x, a23.y};
            unsigned long long br[4] = {b01.x, b01.y, b23.x, b23.y};
#pragma unroll
            for (int i = 0; i < 4; i++)
#pragma unroll
                for (int j = 0; j < 4; j++)
                    ffma2(acc[i][j], ar[i], br[j]);
        }

        if (c + 1 < NCHUNK) {
            char* sn = smem + ((c + 1) & 1) * STAGE_B;
            *(float2*)(sn + (kp + 0) * APITCH + prow * 8) = make_float2(xa.x, xa.x);
            *(float2*)(sn + (kp + 1) * APITCH + prow * 8) = make_float2(xa.y, xa.y);
            *(float*)(sn + XS_B + (kp + 0) * WPITCH + prow * 4) = wa.x;
            *(float*)(sn + XS_B + (kp + 1) * WPITCH + prow * 4) = wa.y;
        }
    }

    // ---- epilogue: unpack accumulators -> smem logits ----
    __syncthreads();
    float* L = (float*)smem;   // [128][LPITCH]
#pragma unroll
    for (int i = 0; i < 4; i++) {
        const int r = ty * 4 + i;
#pragma unroll
        for (int j = 0; j < 4; j++) {
            float2 v = *(float2*)&acc[i][j];         // (expert e, e+1)
            *(float2*)&L[r * LPITCH + tx * 8 + j * 2] = v;
        }
    }
    __syncthreads();

    // ---- fused top-k: warp w handles rows w*8 .. w*8+7 ----
    float bv[4];
#pragma unroll
    for (int q = 0; q < 4; q++) bv[q] = bias[q * 32 + lane];

    for (int rr = 0; rr < 8; rr++) {
        const int row = wid * 8 + rr;
        const float* Lr = L + row * LPITCH;

        float sv[4], wv[4];
#pragma unroll
        for (int q = 0; q < 4; q++) {
            float sc = 1.f / (1.f + expf(-Lr[q * 32 + lane]));
            wv[q] = sc;
            sv[q] = sc + bv[q];
        }

        float wsel[TOPK];
        int   isel[TOPK];
        float wsum = 0.f;
#pragma unroll
        for (int k = 0; k < TOPK; k++) {
            float bs = -INFINITY; int bi = 0x7fffffff; float bw = 0.f;
#pragma unroll
            for (int q = 0; q < 4; q++) {
                int e = q * 32 + lane;
                if (sv[q] > bs || (sv[q] == bs && e < bi)) { bs = sv[q]; bi = e; bw = wv[q]; }
            }
#pragma unroll
            for (int off = 16; off; off >>= 1) {
                float os = __shfl_xor_sync(0xffffffffu, bs, off);
                int   oi = __shfl_xor_sync(0xffffffffu, bi, off);
                float ow = __shfl_xor_sync(0xffffffffu, bw, off);
                if (os > bs || (os == bs && oi < bi)) { bs = os; bi = oi; bw = ow; }
            }
            isel[k] = bi; wsel[k] = bw; wsum += bw;
#pragma unroll
            for (int q = 0; q < 4; q++)
                if (q * 32 + lane == bi) sv[q] = -INFINITY;
        }

        if (lane == 0) {
            const int token = m0 + row;
            float inv = 1.f / (wsum + 1e-20f);   // ROUTED_SCALING = 1.0
#pragma unroll
            for (int k = 0; k < TOPK; k++) {
                out[(size_t)token * TOPK + k]                    = (float)isel[k];
                out[(size_t)T * TOPK + (size_t)token * TOPK + k] = wsel[k] * inv;
            }
        }
    }
}

// ---------------------------------------------------------------------------
extern "C" void kernel_launch(void* const* d_in, const int* in_sizes, int n_in,
                              void* d_out, int out_size)
{
    const float* X    = (const float*)d_in[0];   // hidden_states [T, 4096]
    const float* W    = (const float*)d_in[1];   // weight [128, 4096]
    const float* bias = (const float*)d_in[2];   // e_score_correction_bias [128]
    float* out = (float*)d_out;

    const int T = in_sizes[0] / HIDDEN;          // 16384

    cudaFuncSetAttribute(router_fused,
                         cudaFuncAttributeMaxDynamicSharedMemorySize, SMEM_BYTES);
    router_fused<<<T / TM, NTHR, SMEM_BYTES>>>(X, W, bias, out, T);
}

// round 8
// speedup vs baseline: 1.2306x; 1.2306x over previous
#include <cuda_runtime.h>
#include <math.h>
#include <stdint.h>

#define HIDDEN 4096
#define NEXP   128
#define TOPK   8
#define TM     128
#define KCH    32
#define NCHUNK (HIDDEN / KCH)

#define PITCH   36                    // bytes per 8-float row (9 float slots)
#define K8S     (128 * PITCH + 32)    // 4640 B per k8 region (+32B bank skew)
#define AREG    (4 * K8S)             // A region per stage
#define STAGE_B (2 * AREG)            // A + B per stage
#define LPITCH  132                   // logits smem pitch (floats)
#define SMEM_BYTES (2 * STAGE_B)

#define DELTA   1.5e-4f               // near-tie threshold on selection scores
#define RB      8                     // refine batch (tokens per CTA pass)

__device__ int g_ctr;
__device__ int g_list[16384];

// round-to-nearest tf32 split: h exactly representable in tf32, l = x-h exact
__device__ __forceinline__ void split_tf32(float x, uint32_t& h, uint32_t& l) {
    uint32_t hb = (__float_as_uint(x) + 0x1000u) & 0xFFFFE000u;
    h = hb;
    l = __float_as_uint(x - __uint_as_float(hb));
}

__device__ __forceinline__ void mma8(float d[4], const uint32_t a[4], const uint32_t b[2]) {
    asm volatile(
        "mma.sync.aligned.m16n8k8.row.col.f32.tf32.tf32.f32 "
        "{%0,%1,%2,%3}, {%4,%5,%6,%7}, {%8,%9}, {%0,%1,%2,%3};\n"
        : "+f"(d[0]), "+f"(d[1]), "+f"(d[2]), "+f"(d[3])
        : "r"(a[0]), "r"(a[1]), "r"(a[2]), "r"(a[3]),
          "r"(b[0]), "r"(b[1]));
}

__global__ void zero_ctr_kernel() { g_ctr = 0; }

// ---------------------------------------------------------------------------
// Kernel A: tf32x3 mma.sync GEMM (logits = X @ W^T) with latency-friendly
// pass ordering -> smem logits -> sigmoid -> top-9 risk detection -> write
// provisional top-8; risky tokens appended to g_list for exact fp32 refine.
// ---------------------------------------------------------------------------
__global__ void __launch_bounds__(256, 1) router_fused(
    const float* __restrict__ X, const float* __restrict__ W,
    const float* __restrict__ bias, float* __restrict__ out, int T)
{
    extern __shared__ char smem[];
    const int tid  = threadIdx.x;
    const int wid  = tid >> 5;
    const int lane = tid & 31;
    const int m0   = blockIdx.x * TM;
    const int wm   = wid >> 2;            // 0..1
    const int wn   = wid & 3;             // 0..3
    const int g    = lane >> 2;           // groupID
    const int t    = lane & 3;            // threadID_in_group

    const int c4   = tid & 7;
    const int k8p  = c4 >> 1;
    const int kkb  = (c4 & 1) * 4;

    float acc[4][4][4];
#pragma unroll
    for (int i = 0; i < 4; i++)
#pragma unroll
        for (int j = 0; j < 4; j++)
#pragma unroll
            for (int q = 0; q < 4; q++) acc[i][j][q] = 0.f;

    float4 xa[4], wa[4];

#pragma unroll
    for (int i = 0; i < 4; i++) {
        const int row = (tid >> 3) + 32 * i;
        xa[i] = *(const float4*)(X + (size_t)(m0 + row) * HIDDEN + c4 * 4);
        wa[i] = *(const float4*)(W + (size_t)row * HIDDEN + c4 * 4);
    }
#pragma unroll
    for (int i = 0; i < 4; i++) {
        const int row = (tid >> 3) + 32 * i;
        float* pA = (float*)(smem + k8p * K8S + row * PITCH + kkb * 4);
        pA[0] = xa[i].x; pA[1] = xa[i].y; pA[2] = xa[i].z; pA[3] = xa[i].w;
        float* pB = (float*)(smem + AREG + k8p * K8S + row * PITCH + kkb * 4);
        pB[0] = wa[i].x; pB[1] = wa[i].y; pB[2] = wa[i].z; pB[3] = wa[i].w;
    }

    for (int c = 0; c < NCHUNK; c++) {
        __syncthreads();
        const char* sp = smem + (c & 1) * STAGE_B;

        if (c + 1 < NCHUNK) {
            const int k0 = (c + 1) * KCH;
#pragma unroll
            for (int i = 0; i < 4; i++) {
                const int row = (tid >> 3) + 32 * i;
                xa[i] = *(const float4*)(X + (size_t)(m0 + row) * HIDDEN + k0 + c4 * 4);
                wa[i] = *(const float4*)(W + (size_t)row * HIDDEN + k0 + c4 * 4);
            }
        }

#pragma unroll
        for (int k8 = 0; k8 < 4; k8++) {
            // load + split ALL fragments for this k8 into registers first
            const char* sB = sp + AREG + k8 * K8S + wn * (32 * PITCH);
            uint32_t bh[4][2], bl[4][2];
#pragma unroll
            for (int j = 0; j < 4; j++) {
                float b0 = *(const float*)(sB + (j * 8 + g) * PITCH + t * 4);
                float b1 = *(const float*)(sB + (j * 8 + g) * PITCH + (t + 4) * 4);
                split_tf32(b0, bh[j][0], bl[j][0]);
                split_tf32(b1, bh[j][1], bl[j][1]);
            }
            const char* sA = sp + k8 * K8S + wm * (64 * PITCH);
            uint32_t ah[4][4], al[4][4];
#pragma unroll
            for (int i = 0; i < 4; i++) {
                float a0 = *(const float*)(sA + (i * 16 + g)     * PITCH + t * 4);
                float a1 = *(const float*)(sA + (i * 16 + g + 8) * PITCH + t * 4);
                float a2 = *(const float*)(sA + (i * 16 + g)     * PITCH + (t + 4) * 4);
                float a3 = *(const float*)(sA + (i * 16 + g + 8) * PITCH + (t + 4) * 4);
                split_tf32(a0, ah[i][0], al[i][0]);
                split_tf32(a1, ah[i][1], al[i][1]);
                split_tf32(a2, ah[i][2], al[i][2]);
                split_tf32(a3, ah[i][3], al[i][3]);
            }
            // pass 1: hi*hi over all 16 accumulators (independent chains)
#pragma unroll
            for (int i = 0; i < 4; i++)
#pragma unroll
                for (int j = 0; j < 4; j++)
                    mma8(acc[i][j], ah[i], bh[j]);
            // pass 2: lo*hi
#pragma unroll
            for (int i = 0; i < 4; i++)
#pragma unroll
                for (int j = 0; j < 4; j++)
                    mma8(acc[i][j], al[i], bh[j]);
            // pass 3: hi*lo
#pragma unroll
            for (int i = 0; i < 4; i++)
#pragma unroll
                for (int j = 0; j < 4; j++)
                    mma8(acc[i][j], ah[i], bl[j]);
        }

        if (c + 1 < NCHUNK) {
            char* sn = smem + ((c + 1) & 1) * STAGE_B;
#pragma unroll
            for (int i = 0; i < 4; i++) {
                const int row = (tid >> 3) + 32 * i;
                float* pA = (float*)(sn + k8p * K8S + row * PITCH + kkb * 4);
                pA[0] = xa[i].x; pA[1] = xa[i].y; pA[2] = xa[i].z; pA[3] = xa[i].w;
                float* pB = (float*)(sn + AREG + k8p * K8S + row * PITCH + kkb * 4);
                pB[0] = wa[i].x; pB[1] = wa[i].y; pB[2] = wa[i].z; pB[3] = wa[i].w;
            }
        }
    }

    // ---- accumulators -> smem logits ----
    __syncthreads();
    float* L = (float*)smem;   // [128][LPITCH]
#pragma unroll
    for (int i = 0; i < 4; i++) {
        const int r0 = wm * 64 + i * 16 + g;
#pragma unroll
        for (int j = 0; j < 4; j++) {
            const int c0 = wn * 32 + j * 8 + t * 2;
            *(float2*)&L[r0 * LPITCH + c0]       = make_float2(acc[i][j][0], acc[i][j][1]);
            *(float2*)&L[(r0 + 8) * LPITCH + c0] = make_float2(acc[i][j][2], acc[i][j][3]);
        }
    }
    __syncthreads();

    // ---- top-9 with risk detection; warp w handles rows w*16..w*16+15 ----
    float bv[4];
#pragma unroll
    for (int q = 0; q < 4; q++) bv[q] = bias[q * 32 + lane];

    for (int rr = 0; rr < 16; rr++) {
        const int row = wid * 16 + rr;
        const float* Lr = L + row * LPITCH;

        float sv[4], wv[4];
#pragma unroll
        for (int q = 0; q < 4; q++) {
            float sc = 1.f / (1.f + expf(-Lr[q * 32 + lane]));
            wv[q] = sc;
            sv[q] = sc + bv[q];
        }

        float wsel[TOPK];
        int   isel[TOPK];
        float wsum = 0.f;
        float prev = 0.f, mingap = INFINITY;

#pragma unroll
        for (int k = 0; k < TOPK + 1; k++) {
            float bs = -INFINITY; int bi = 0x7fffffff; float bw = 0.f;
#pragma unroll
            for (int q = 0; q < 4; q++) {
                int e = q * 32 + lane;
                if (sv[q] > bs || (sv[q] == bs && e < bi)) { bs = sv[q]; bi = e; bw = wv[q]; }
            }
#pragma unroll
            for (int off = 16; off; off >>= 1) {
                float os = __shfl_xor_sync(0xffffffffu, bs, off);
                int   oi = __shfl_xor_sync(0xffffffffu, bi, off);
                float ow = __shfl_xor_sync(0xffffffffu, bw, off);
                if (os > bs || (os == bs && oi < bi)) { bs = os; bi = oi; bw = ow; }
            }
            if (k > 0) mingap = fminf(mingap, prev - bs);
            prev = bs;
            if (k < TOPK) {
                isel[k] = bi; wsel[k] = bw; wsum += bw;
#pragma unroll
                for (int q = 0; q < 4; q++)
                    if (q * 32 + lane == bi) sv[q] = -INFINITY;
            }
        }

        if (lane == 0) {
            const int token = m0 + row;
            float inv = 1.f / (wsum + 1e-20f);   // ROUTED_SCALING = 1.0
#pragma unroll
            for (int k = 0; k < TOPK; k++) {
                out[(size_t)token * TOPK + k]                    = (float)isel[k];
                out[(size_t)T * TOPK + (size_t)token * TOPK + k] = wsel[k] * inv;
            }
            if (!(mingap >= DELTA)) {                 // near tie (or NaN) -> refine
                int idx = atomicAdd(&g_ctr, 1);
                g_list[idx] = token;
            }
        }
    }
}

// ---------------------------------------------------------------------------
// Kernel C: exact fp32 refine of risky tokens (unchanged, proven).
// ---------------------------------------------------------------------------
__global__ void __launch_bounds__(256) refine_kernel(
    const float* __restrict__ X, const float* __restrict__ W,
    const float* __restrict__ bias, float* __restrict__ out, int T)
{
    __shared__ float Xs[RB][512];
    __shared__ float S[RB][NEXP];
    __shared__ int   tks[RB];

    const int tid  = threadIdx.x;
    const int e    = tid & 127;
    const int tg   = tid >> 7;
    const int wid  = tid >> 5;
    const int lane = tid & 31;
    const int R    = g_ctr;

    for (int b = blockIdx.x; b * RB < R; b += gridDim.x) {
        if (tid < RB) {
            int i = b * RB + tid;
            tks[tid] = (i < R) ? g_list[i] : -1;
        }
        __syncthreads();

        float acc[4] = {0.f, 0.f, 0.f, 0.f};
        const float* wrow = W + (size_t)e * HIDDEN;

        for (int c = 0; c < 8; c++) {
            const int k0 = c * 512;
#pragma unroll
            for (int i = 0; i < 4; i++) {
                int s   = tid + 256 * i;
                int tok = s >> 7;
                int f4  = s & 127;
                int tt  = tks[tok] < 0 ? 0 : tks[tok];
                *(float4*)&Xs[tok][f4 * 4] =
                    *(const float4*)(X + (size_t)tt * HIDDEN + k0 + f4 * 4);
            }
            __syncthreads();
#pragma unroll 4
            for (int f4 = 0; f4 < 128; f4++) {
                float4 w4 = *(const float4*)(wrow + k0 + f4 * 4);
#pragma unroll
                for (int j = 0; j < 4; j++) {
                    const float* xr = &Xs[tg * 4 + j][f4 * 4];
                    acc[j] = fmaf(w4.x, xr[0],
                             fmaf(w4.y, xr[1],
                             fmaf(w4.z, xr[2],
                             fmaf(w4.w, xr[3], acc[j]))));
                }
            }
            __syncthreads();
        }
#pragma unroll
        for (int j = 0; j < 4; j++) S[tg * 4 + j][e] = acc[j];
        __syncthreads();

        if (wid < RB && tks[wid] >= 0) {
            const int token = tks[wid];
            float sv[4], wv[4];
#pragma unroll
            for (int q = 0; q < 4; q++) {
                int ee = q * 32 + lane;
                float sc = 1.f / (1.f + expf(-S[wid][ee]));
                wv[q] = sc;
                sv[q] = sc + bias[ee];
            }
            float wsel[TOPK]; int isel[TOPK]; float wsum = 0.f;
#pragma unroll
            for (int k = 0; k < TOPK; k++) {
                float bs = -INFINITY; int bi = 0x7fffffff; float bw = 0.f;
#pragma unroll
                for (int q = 0; q < 4; q++) {
                    int ee = q * 32 + lane;
                    if (sv[q] > bs || (sv[q] == bs && ee < bi)) { bs = sv[q]; bi = ee; bw = wv[q]; }
                }
#pragma unroll
                for (int off = 16; off; off >>= 1) {
                    float os = __shfl_xor_sync(0xffffffffu, bs, off);
                    int   oi = __shfl_xor_sync(0xffffffffu, bi, off);
                    float ow = __shfl_xor_sync(0xffffffffu, bw, off);
                    if (os > bs || (os == bs && oi < bi)) { bs = os; bi = oi; bw = ow; }
                }
                isel[k] = bi; wsel[k] = bw; wsum += bw;
#pragma unroll
                for (int q = 0; q < 4; q++)
                    if (q * 32 + lane == bi) sv[q] = -INFINITY;
            }
            if (lane == 0) {
                float inv = 1.f / (wsum + 1e-20f);
#pragma unroll
                for (int k = 0; k < TOPK; k++) {
                    out[(size_t)token * TOPK + k]                    = (float)isel[k];
                    out[(size_t)T * TOPK + (size_t)token * TOPK + k] = wsel[k] * inv;
                }
            }
        }
        __syncthreads();
    }
}

// ---------------------------------------------------------------------------
extern "C" void kernel_launch(void* const* d_in, const int* in_sizes, int n_in,
                              void* d_out, int out_size)
{
    const float* X    = (const float*)d_in[0];   // hidden_states [T, 4096]
    const float* W    = (const float*)d_in[1];   // weight [128, 4096]
    const float* bias = (const float*)d_in[2];   // e_score_correction_bias [128]
    float* out = (float*)d_out;

    const int T = in_sizes[0] / HIDDEN;          // 16384

    cudaFuncSetAttribute(router_fused,
                         cudaFuncAttributeMaxDynamicSharedMemorySize, SMEM_BYTES);

    zero_ctr_kernel<<<1, 1>>>();
    router_fused<<<T / TM, 256, SMEM_BYTES>>>(X, W, bias, out, T);
    refine_kernel<<<256, 256>>>(X, W, bias, out, T);
}

// round 10
// speedup vs baseline: 1.3949x; 1.1335x over previous
#include <cuda_runtime.h>
#include <math.h>
#include <stdint.h>

#define HIDDEN 4096
#define NEXP   128
#define TOPK   8
#define TM     128
#define KCH    32
#define NCHUNK (HIDDEN / KCH)

#define PITCH   36                    // bytes per 8-float row (9 float slots)
#define K8S     (128 * PITCH + 32)    // 4640 B per k8 region (+32B bank skew)
#define AREG    (4 * K8S)             // A region per stage
#define STAGE_B (2 * AREG)            // A + B per stage
#define LPITCH  132                   // logits smem pitch (floats)
#define SMEM_BYTES (2 * STAGE_B)

#define DELTA   1.5e-4f               // near-tie threshold on selection scores
#define RB      8                     // refine batch (tokens per CTA pass)

__device__ int g_ctr;
__device__ int g_list[16384];

// Split adjacent-k float pair into packed bf16x2 hi and exact-residual lo.
// reg.lo = element k (x), reg.hi = element k+1 (y) — mma fragment order.
__device__ __forceinline__ void split_bf16(float x, float y, uint32_t& h, uint32_t& l) {
    asm("cvt.rn.bf16x2.f32 %0, %1, %2;" : "=r"(h) : "f"(y), "f"(x));
    float h0 = __uint_as_float(h << 16);
    float h1 = __uint_as_float(h & 0xffff0000u);
    asm("cvt.rn.bf16x2.f32 %0, %1, %2;" : "=r"(l) : "f"(y - h1), "f"(x - h0));
}

__device__ __forceinline__ void mma16(float d[4], const uint32_t a[4], const uint32_t b[2]) {
    asm volatile(
        "mma.sync.aligned.m16n8k16.row.col.f32.bf16.bf16.f32 "
        "{%0,%1,%2,%3}, {%4,%5,%6,%7}, {%8,%9}, {%0,%1,%2,%3};\n"
        : "+f"(d[0]), "+f"(d[1]), "+f"(d[2]), "+f"(d[3])
        : "r"(a[0]), "r"(a[1]), "r"(a[2]), "r"(a[3]),
          "r"(b[0]), "r"(b[1]));
}

__global__ void zero_ctr_kernel() { g_ctr = 0; }

// ---------------------------------------------------------------------------
// Kernel A: bf16x3 (hi/lo split, 3-pass) m16n8k16 mma GEMM (logits = X @ W^T)
// -> smem logits -> sigmoid -> top-9 risk detection -> provisional top-8.
// Risky tokens (near ties) appended to g_list for exact fp32 refine.
// All smem loads are scalar 4-byte (layout pitch 36 B is not 8B-aligned).
// ---------------------------------------------------------------------------
__global__ void __launch_bounds__(256, 1) router_fused(
    const float* __restrict__ X, const float* __restrict__ W,
    const float* __restrict__ bias, float* __restrict__ out, int T)
{
    extern __shared__ char smem[];
    const int tid  = threadIdx.x;
    const int wid  = tid >> 5;
    const int lane = tid & 31;
    const int m0   = blockIdx.x * TM;
    const int wm   = wid >> 2;            // 0..1
    const int wn   = wid & 3;             // 0..3
    const int g    = lane >> 2;           // groupID
    const int t    = lane & 3;            // threadID_in_group

    const int c4   = tid & 7;
    const int k8p  = c4 >> 1;
    const int kkb  = (c4 & 1) * 4;

    float acc[4][4][4];
#pragma unroll
    for (int i = 0; i < 4; i++)
#pragma unroll
        for (int j = 0; j < 4; j++)
#pragma unroll
            for (int q = 0; q < 4; q++) acc[i][j][q] = 0.f;

    float4 xa[4], wa[4];

#pragma unroll
    for (int i = 0; i < 4; i++) {
        const int row = (tid >> 3) + 32 * i;
        xa[i] = *(const float4*)(X + (size_t)(m0 + row) * HIDDEN + c4 * 4);
        wa[i] = *(const float4*)(W + (size_t)row * HIDDEN + c4 * 4);
    }
#pragma unroll
    for (int i = 0; i < 4; i++) {
        const int row = (tid >> 3) + 32 * i;
        float* pA = (float*)(smem + k8p * K8S + row * PITCH + kkb * 4);
        pA[0] = xa[i].x; pA[1] = xa[i].y; pA[2] = xa[i].z; pA[3] = xa[i].w;
        float* pB = (float*)(smem + AREG + k8p * K8S + row * PITCH + kkb * 4);
        pB[0] = wa[i].x; pB[1] = wa[i].y; pB[2] = wa[i].z; pB[3] = wa[i].w;
    }

    for (int c = 0; c < NCHUNK; c++) {
        __syncthreads();
        const char* sp = smem + (c & 1) * STAGE_B;

        if (c + 1 < NCHUNK) {
            const int k0 = (c + 1) * KCH;
#pragma unroll
            for (int i = 0; i < 4; i++) {
                const int row = (tid >> 3) + 32 * i;
                xa[i] = *(const float4*)(X + (size_t)(m0 + row) * HIDDEN + k0 + c4 * 4);
                wa[i] = *(const float4*)(W + (size_t)row * HIDDEN + k0 + c4 * 4);
            }
        }

        // two k16 halves per 32-wide chunk; each spans two k8 regions
#pragma unroll
        for (int h = 0; h < 2; h++) {
            const char* a0p = sp + (2 * h + 0) * K8S + wm * (64 * PITCH);
            const char* a1p = sp + (2 * h + 1) * K8S + wm * (64 * PITCH);
            const char* b0p = sp + AREG + (2 * h + 0) * K8S + wn * (32 * PITCH);
            const char* b1p = sp + AREG + (2 * h + 1) * K8S + wn * (32 * PITCH);

            uint32_t bh[4][2], bl[4][2];
#pragma unroll
            for (int j = 0; j < 4; j++) {
                const char* r0 = b0p + (j * 8 + g) * PITCH + t * 8;
                const char* r1 = b1p + (j * 8 + g) * PITCH + t * 8;
                split_bf16(*(const float*)(r0), *(const float*)(r0 + 4),
                           bh[j][0], bl[j][0]);       // k = 2t, 2t+1
                split_bf16(*(const float*)(r1), *(const float*)(r1 + 4),
                           bh[j][1], bl[j][1]);       // k = 2t+8, 2t+9
            }
            uint32_t ah[4][4], al[4][4];
#pragma unroll
            for (int i = 0; i < 4; i++) {
                const char* q0 = a0p + (i * 16 + g)     * PITCH + t * 8;
                const char* q1 = a0p + (i * 16 + g + 8) * PITCH + t * 8;
                const char* q2 = a1p + (i * 16 + g)     * PITCH + t * 8;
                const char* q3 = a1p + (i * 16 + g + 8) * PITCH + t * 8;
                split_bf16(*(const float*)(q0), *(const float*)(q0 + 4),
                           ah[i][0], al[i][0]);       // (g,   2t..2t+1)
                split_bf16(*(const float*)(q1), *(const float*)(q1 + 4),
                           ah[i][1], al[i][1]);       // (g+8, 2t..2t+1)
                split_bf16(*(const float*)(q2), *(const float*)(q2 + 4),
                           ah[i][2], al[i][2]);       // (g,   2t+8..9)
                split_bf16(*(const float*)(q3), *(const float*)(q3 + 4),
                           ah[i][3], al[i][3]);       // (g+8, 2t+8..9)
            }
            // pass 1: hi*hi
#pragma unroll
            for (int i = 0; i < 4; i++)
#pragma unroll
                for (int j = 0; j < 4; j++)
                    mma16(acc[i][j], ah[i], bh[j]);
            // pass 2: lo*hi
#pragma unroll
            for (int i = 0; i < 4; i++)
#pragma unroll
                for (int j = 0; j < 4; j++)
                    mma16(acc[i][j], al[i], bh[j]);
            // pass 3: hi*lo
#pragma unroll
            for (int i = 0; i < 4; i++)
#pragma unroll
                for (int j = 0; j < 4; j++)
                    mma16(acc[i][j], ah[i], bl[j]);
        }

        if (c + 1 < NCHUNK) {
            char* sn = smem + ((c + 1) & 1) * STAGE_B;
#pragma unroll
            for (int i = 0; i < 4; i++) {
                const int row = (tid >> 3) + 32 * i;
                float* pA = (float*)(sn + k8p * K8S + row * PITCH + kkb * 4);
                pA[0] = xa[i].x; pA[1] = xa[i].y; pA[2] = xa[i].z; pA[3] = xa[i].w;
                float* pB = (float*)(sn + AREG + k8p * K8S + row * PITCH + kkb * 4);
                pB[0] = wa[i].x; pB[1] = wa[i].y; pB[2] = wa[i].z; pB[3] = wa[i].w;
            }
        }
    }

    // ---- accumulators -> smem logits ----
    __syncthreads();
    float* L = (float*)smem;   // [128][LPITCH]
#pragma unroll
    for (int i = 0; i < 4; i++) {
        const int r0 = wm * 64 + i * 16 + g;
#pragma unroll
        for (int j = 0; j < 4; j++) {
            const int c0 = wn * 32 + j * 8 + t * 2;
            *(float2*)&L[r0 * LPITCH + c0]       = make_float2(acc[i][j][0], acc[i][j][1]);
            *(float2*)&L[(r0 + 8) * LPITCH + c0] = make_float2(acc[i][j][2], acc[i][j][3]);
        }
    }
    __syncthreads();

    // ---- top-9 with risk detection; warp w handles rows w*16..w*16+15 ----
    float bv[4];
#pragma unroll
    for (int q = 0; q < 4; q++) bv[q] = bias[q * 32 + lane];

    for (int rr = 0; rr < 16; rr++) {
        const int row = wid * 16 + rr;
        const float* Lr = L + row * LPITCH;

        float sv[4], wv[4];
#pragma unroll
        for (int q = 0; q < 4; q++) {
            float sc = 1.f / (1.f + expf(-Lr[q * 32 + lane]));
            wv[q] = sc;
            sv[q] = sc + bv[q];
        }

        float wsel[TOPK];
        int   isel[TOPK];
        float wsum = 0.f;
        float prev = 0.f, mingap = INFINITY;

#pragma unroll
        for (int k = 0; k < TOPK + 1; k++) {
            float bs = -INFINITY; int bi = 0x7fffffff; float bw = 0.f;
#pragma unroll
            for (int q = 0; q < 4; q++) {
                int e = q * 32 + lane;
                if (sv[q] > bs || (sv[q] == bs && e < bi)) { bs = sv[q]; bi = e; bw = wv[q]; }
            }
#pragma unroll
            for (int off = 16; off; off >>= 1) {
                float os = __shfl_xor_sync(0xffffffffu, bs, off);
                int   oi = __shfl_xor_sync(0xffffffffu, bi, off);
                float ow = __shfl_xor_sync(0xffffffffu, bw, off);
                if (os > bs || (os == bs && oi < bi)) { bs = os; bi = oi; bw = ow; }
            }
            if (k > 0) mingap = fminf(mingap, prev - bs);
            prev = bs;
            if (k < TOPK) {
                isel[k] = bi; wsel[k] = bw; wsum += bw;
#pragma unroll
                for (int q = 0; q < 4; q++)
                    if (q * 32 + lane == bi) sv[q] = -INFINITY;
            }
        }

        if (lane == 0) {
            const int token = m0 + row;
            float inv = 1.f / (wsum + 1e-20f);   // ROUTED_SCALING = 1.0
#pragma unroll
            for (int k = 0; k < TOPK; k++) {
                out[(size_t)token * TOPK + k]                    = (float)isel[k];
                out[(size_t)T * TOPK + (size_t)token * TOPK + k] = wsel[k] * inv;
            }
            if (!(mingap >= DELTA)) {                 // near tie (or NaN) -> refine
                int idx = atomicAdd(&g_ctr, 1);
                g_list[idx] = token;
            }
        }
    }
}

// ---------------------------------------------------------------------------
// Kernel C: exact fp32 refine of risky tokens (unchanged, proven).
// ---------------------------------------------------------------------------
__global__ void __launch_bounds__(256) refine_kernel(
    const float* __restrict__ X, const float* __restrict__ W,
    const float* __restrict__ bias, float* __restrict__ out, int T)
{
    __shared__ float Xs[RB][512];
    __shared__ float S[RB][NEXP];
    __shared__ int   tks[RB];

    const int tid  = threadIdx.x;
    const int e    = tid & 127;
    const int tg   = tid >> 7;
    const int wid  = tid >> 5;
    const int lane = tid & 31;
    const int R    = g_ctr;

    for (int b = blockIdx.x; b * RB < R; b += gridDim.x) {
        if (tid < RB) {
            int i = b * RB + tid;
            tks[tid] = (i < R) ? g_list[i] : -1;
        }
        __syncthreads();

        float acc[4] = {0.f, 0.f, 0.f, 0.f};
        const float* wrow = W + (size_t)e * HIDDEN;

        for (int c = 0; c < 8; c++) {
            const int k0 = c * 512;
#pragma unroll
            for (int i = 0; i < 4; i++) {
                int s   = tid + 256 * i;
                int tok = s >> 7;
                int f4  = s & 127;
                int tt  = tks[tok] < 0 ? 0 : tks[tok];
                *(float4*)&Xs[tok][f4 * 4] =
                    *(const float4*)(X + (size_t)tt * HIDDEN + k0 + f4 * 4);
            }
            __syncthreads();
#pragma unroll 4
            for (int f4 = 0; f4 < 128; f4++) {
                float4 w4 = *(const float4*)(wrow + k0 + f4 * 4);
#pragma unroll
                for (int j = 0; j < 4; j++) {
                    const float* xr = &Xs[tg * 4 + j][f4 * 4];
                    acc[j] = fmaf(w4.x, xr[0],
                             fmaf(w4.y, xr[1],
                             fmaf(w4.z, xr[2],
                             fmaf(w4.w, xr[3], acc[j]))));
                }
            }
            __syncthreads();
        }
#pragma unroll
        for (int j = 0; j < 4; j++) S[tg * 4 + j][e] = acc[j];
        __syncthreads();

        if (wid < RB && tks[wid] >= 0) {
            const int token = tks[wid];
            float sv[4], wv[4];
#pragma unroll
            for (int q = 0; q < 4; q++) {
                int ee = q * 32 + lane;
                float sc = 1.f / (1.f + expf(-S[wid][ee]));
                wv[q] = sc;
                sv[q] = sc + bias[ee];
            }
            float wsel[TOPK]; int isel[TOPK]; float wsum = 0.f;
#pragma unroll
            for (int k = 0; k < TOPK; k++) {
                float bs = -INFINITY; int bi = 0x7fffffff; float bw = 0.f;
#pragma unroll
                for (int q = 0; q < 4; q++) {
                    int ee = q * 32 + lane;
                    if (sv[q] > bs || (sv[q] == bs && ee < bi)) { bs = sv[q]; bi = ee; bw = wv[q]; }
                }
#pragma unroll
                for (int off = 16; off; off >>= 1) {
                    float os = __shfl_xor_sync(0xffffffffu, bs, off);
                    int   oi = __shfl_xor_sync(0xffffffffu, bi, off);
                    float ow = __shfl_xor_sync(0xffffffffu, bw, off);
                    if (os > bs || (os == bs && oi < bi)) { bs = os; bi = oi; bw = ow; }
                }
                isel[k] = bi; wsel[k] = bw; wsum += bw;
#pragma unroll
                for (int q = 0; q < 4; q++)
                    if (q * 32 + lane == bi) sv[q] = -INFINITY;
            }
            if (lane == 0) {
                float inv = 1.f / (wsum + 1e-20f);
#pragma unroll
                for (int k = 0; k < TOPK; k++) {
                    out[(size_t)token * TOPK + k]                    = (float)isel[k];
                    out[(size_t)T * TOPK + (size_t)token * TOPK + k] = wsel[k] * inv;
                }
            }
        }
        __syncthreads();
    }
}

// ---------------------------------------------------------------------------
extern "C" void kernel_launch(void* const* d_in, const int* in_sizes, int n_in,
                              void* d_out, int out_size)
{
    const float* X    = (const float*)d_in[0];   // hidden_states [T, 4096]
    const float* W    = (const float*)d_in[1];   // weight [128, 4096]
    const float* bias = (const float*)d_in[2];   // e_score_correction_bias [128]
    float* out = (float*)d_out;

    const int T = in_sizes[0] / HIDDEN;          // 16384

    cudaFuncSetAttribute(router_fused,
                         cudaFuncAttributeMaxDynamicSharedMemorySize, SMEM_BYTES);

    zero_ctr_kernel<<<1, 1>>>();
    router_fused<<<T / TM, 256, SMEM_BYTES>>>(X, W, bias, out, T);
    refine_kernel<<<256, 256>>>(X, W, bias, out, T);
}